// round 7
// baseline (speedup 1.0000x reference)
#include <cuda_runtime.h>
#include <math.h>

#define BB   512
#define LLN  64
#define NEE  128
#define DD   128
#define NEGV (-9e15f)
#define NOUT ((size_t)BB * LLN * DD)

// smem layout (float offsets)
#define OFF_XS    0              // 8192 : x (64x128)
#define OFF_XT    8192           // 8192 : transferred x (64x128)
#define OFF_EDGE  16384          // 16384: edge (128x128), also stages g2w
#define OFF_ATT   32768          // 8448 : att1[64][130] / att2[128][66] / split-K scratch
#define OFF_E1    41216          // 64
#define OFF_F1    41280          // 64
#define OFF_F2    41344          // 128
#define OFF_ADJ   41472          // u64[128] (256 floats)
#define SMEM_BYTES ((41728 + 32) * 4)

#define P1PITCH 130              // att1 row pitch (floats)
#define P2PITCH 66               // att2 row pitch (floats)

typedef unsigned long long u64;

// Per-layer precomputed projection vectors
__device__ float g_u1[2][DD];   // w2 @ a[d:2d]
__device__ float g_u2[2][DD];   // w2 @ a2[0:d]
__device__ float g_v3[2][DD];   // w3 @ a2[d:2d]
__device__ float g_qa[2];       // q . a[0:d]

__global__ void precompute_kernel(
    const float* __restrict__ w2_1, const float* __restrict__ w3_1,
    const float* __restrict__ q_1,  const float* __restrict__ a_1,  const float* __restrict__ a2_1,
    const float* __restrict__ w2_2, const float* __restrict__ w3_2,
    const float* __restrict__ q_2,  const float* __restrict__ a_2,  const float* __restrict__ a2_2)
{
    int k = threadIdx.x;  // 0..127
    const float* w2[2]  = {w2_1, w2_2};
    const float* w3[2]  = {w3_1, w3_2};
    const float* av[2]  = {a_1,  a_2};
    const float* a2v[2] = {a2_1, a2_2};
    const float* qv[2]  = {q_1,  q_2};

    for (int l = 0; l < 2; l++) {
        float u1 = 0.f, u2 = 0.f, v3 = 0.f;
        for (int j = 0; j < DD; j++) {
            float w2kj = w2[l][k * DD + j];
            u1 += w2kj * av[l][DD + j];
            u2 += w2kj * a2v[l][j];
            v3 += w3[l][k * DD + j] * a2v[l][DD + j];
        }
        g_u1[l][k] = u1;
        g_u2[l][k] = u2;
        g_v3[l][k] = v3;
    }
    __shared__ float red[DD];
    for (int l = 0; l < 2; l++) {
        red[k] = qv[l][k] * av[l][k];
        __syncthreads();
        if (k == 0) {
            float s = 0.f;
            for (int i = 0; i < DD; i++) s += red[i];
            g_qa[l] = s;
        }
        __syncthreads();
    }
}

// ---- packed fp32x2 helpers ----
__device__ __forceinline__ u64 fma2(u64 a, u64 b, u64 c) {
    u64 d;
    asm("fma.rn.f32x2 %0, %1, %2, %3;" : "=l"(d) : "l"(a), "l"(b), "l"(c));
    return d;
}
__device__ __forceinline__ u64 add2(u64 a, u64 b) {
    u64 d;
    asm("add.rn.f32x2 %0, %1, %2;" : "=l"(d) : "l"(a), "l"(b));
    return d;
}
__device__ __forceinline__ u64 dup2(float x) {
    u64 d;
    asm("mov.b64 %0, {%1, %2};" : "=l"(d) : "f"(x), "f"(x));
    return d;
}
__device__ __forceinline__ float2 unp2(u64 a) {
    float lo, hi;
    asm("mov.b64 {%0, %1}, %2;" : "=f"(lo), "=f"(hi) : "l"(a));
    return make_float2(lo, hi);
}
__device__ __forceinline__ float wredsum(float v) {
    #pragma unroll
    for (int o = 16; o > 0; o >>= 1) v += __shfl_xor_sync(0xffffffffu, v, o);
    return v;
}
__device__ __forceinline__ float wredmax(float v) {
    #pragma unroll
    for (int o = 16; o > 0; o >>= 1) v = fmaxf(v, __shfl_xor_sync(0xffffffffu, v, o));
    return v;
}
__device__ __forceinline__ u64 wredsum2(u64 v) {
    #pragma unroll
    for (int o = 16; o > 0; o >>= 1) v = add2(v, __shfl_xor_sync(0xffffffffu, v, o));
    return v;
}

// One CTA per batch item, 1024 threads = 32 warps (8 per SMSP for latency hiding).
__global__ void __launch_bounds__(1024, 1) session_main(
    const int*   __restrict__ inputs,   // [B, L]
    const float* __restrict__ HT,       // [B, NE, L]
    const float* __restrict__ emb,      // [V, D]
    const float* __restrict__ emb2,     // [V, D]
    const float* __restrict__ g2w,      // [D, D]
    float*       __restrict__ out)
{
    extern __shared__ float sm[];
    float* xs   = sm + OFF_XS;
    float* xt   = sm + OFF_XT;
    float* edge = sm + OFF_EDGE;
    float* att  = sm + OFF_ATT;
    float* e1   = sm + OFF_E1;
    float* f1   = sm + OFF_F1;
    float* f2   = sm + OFF_F2;
    u64*   adjm = (u64*)(sm + OFF_ADJ);
    u64*   scr  = (u64*)att;            // split-K scratch (att dead at that point)

    const int b = blockIdx.x;
    const int t = threadIdx.x;
    const int w = t >> 5, lane = t & 31;
    const int wg = w & 15, ih = w >> 4;  // split-K: 16 row-groups x 2 k-halves

    // ---- P0: gather x = emb[inputs[b]]; warp owns rows 2w, 2w+1 ----
    #pragma unroll
    for (int r = 0; r < 2; r++) {
        int row = w * 2 + r;
        int idx = __ldg(inputs + b * LLN + row);
        float4 v = __ldg((const float4*)(emb + (size_t)idx * DD) + lane);
        *((float4*)(xs + row * DD) + lane) = v;
    }

    // ---- P1: per-edge node bitmasks; warp owns edges 4w..4w+3 ----
    #pragma unroll
    for (int k = 0; k < 4; k++) {
        int e = w * 4 + k;
        const float* hr = HT + ((size_t)b * NEE + e) * LLN;
        float h0 = __ldg(hr + lane), h1 = __ldg(hr + lane + 32);
        unsigned m0 = __ballot_sync(0xffffffffu, h0 > 0.f);
        unsigned m1 = __ballot_sync(0xffffffffu, h1 > 0.f);
        if (lane == 0) adjm[e] = ((u64)m1 << 32) | (u64)m0;
    }
    __syncthreads();

    for (int l = 0; l < 2; l++) {
        const float* xtp = xs;

        // ---- transfer GEMM (layer 2): xt = xs @ g2w, split-K, row-pair packed ----
        if (l == 1) {
            {
                const float4* src = (const float4*)g2w;
                float4* dst = (float4*)edge;
                #pragma unroll
                for (int r = 0; r < 4; r++)
                    dst[w * 128 + r * 32 + lane] = __ldg(src + w * 128 + r * 32 + lane);
            }
            __syncthreads();
            const int r0 = wg * 4;
            u64 acc[2][4];
            #pragma unroll
            for (int p = 0; p < 2; p++)
                #pragma unroll
                for (int c = 0; c < 4; c++) acc[p][c] = 0;
            const float* xrow0 = xs + (r0 + 0) * DD + ih * 64;
            const float* xrow1 = xs + (r0 + 1) * DD + ih * 64;
            const float* xrow2 = xs + (r0 + 2) * DD + ih * 64;
            const float* xrow3 = xs + (r0 + 3) * DD + ih * 64;
            const float4* wbase = (const float4*)(edge + ih * 64 * DD) + lane;
            #pragma unroll 2
            for (int kk = 0; kk < 64; kk++) {
                float4 wv = wbase[kk * 32];
                u64 bw0 = dup2(wv.x), bw1 = dup2(wv.y), bw2 = dup2(wv.z), bw3 = dup2(wv.w);
                float2 a0 = make_float2(xrow0[kk], xrow1[kk]);
                float2 a1 = make_float2(xrow2[kk], xrow3[kk]);
                u64 ap0 = *(const u64*)&a0;
                u64 ap1 = *(const u64*)&a1;
                acc[0][0] = fma2(ap0, bw0, acc[0][0]); acc[0][1] = fma2(ap0, bw1, acc[0][1]);
                acc[0][2] = fma2(ap0, bw2, acc[0][2]); acc[0][3] = fma2(ap0, bw3, acc[0][3]);
                acc[1][0] = fma2(ap1, bw0, acc[1][0]); acc[1][1] = fma2(ap1, bw1, acc[1][1]);
                acc[1][2] = fma2(ap1, bw2, acc[1][2]); acc[1][3] = fma2(ap1, bw3, acc[1][3]);
            }
            __syncthreads();
            if (ih == 1) {
                #pragma unroll
                for (int p = 0; p < 2; p++)
                    #pragma unroll
                    for (int c = 0; c < 4; c++)
                        scr[wg * 256 + (p * 4 + c) * 32 + lane] = acc[p][c];
            }
            __syncthreads();
            if (ih == 0) {
                #pragma unroll
                for (int p = 0; p < 2; p++) {
                    #pragma unroll
                    for (int c = 0; c < 4; c++)
                        acc[p][c] = add2(acc[p][c], scr[wg * 256 + (p * 4 + c) * 32 + lane]);
                    float2 c0 = unp2(acc[p][0]), c1 = unp2(acc[p][1]);
                    float2 c2 = unp2(acc[p][2]), c3 = unp2(acc[p][3]);
                    *((float4*)(xt + (r0 + 2 * p) * DD) + lane)     = make_float4(c0.x, c1.x, c2.x, c3.x);
                    *((float4*)(xt + (r0 + 2 * p + 1) * DD) + lane) = make_float4(c0.y, c1.y, c2.y, c3.y);
                }
            }
            __syncthreads();
            xtp = xt;
        }

        // ---- P2a: e1[j] = lrelu(qa + xs[j].u1), f1[j] = xs[j].u2 ; warp owns 2 rows ----
        {
            float4 u1v = ((const float4*)g_u1[l])[lane];
            float4 u2v = ((const float4*)g_u2[l])[lane];
            float qa = g_qa[l];
            #pragma unroll
            for (int r = 0; r < 2; r++) {
                int row = w * 2 + r;
                float4 x4 = *((const float4*)(xs + row * DD) + lane);
                float s1 = x4.x * u1v.x + x4.y * u1v.y + x4.z * u1v.z + x4.w * u1v.w;
                float s2 = x4.x * u2v.x + x4.y * u2v.y + x4.z * u2v.z + x4.w * u2v.w;
                s1 = wredsum(s1);
                s2 = wredsum(s2);
                if (lane == 0) {
                    float v = qa + s1;
                    e1[row] = (v > 0.f) ? v : 0.2f * v;
                    f1[row] = s2;
                }
            }
        }
        __syncthreads();

        // ---- P2b: att_edge softmax -> att1[j][e] (pitch 130); warp owns 4 edges ----
        {
            float ev0 = e1[lane], ev1 = e1[lane + 32];
            #pragma unroll
            for (int k = 0; k < 4; k++) {
                int e = w * 4 + k;
                u64 m = adjm[e];
                float v0 = ((m >> lane) & 1ull) ? ev0 : NEGV;
                float v1 = ((m >> (lane + 32)) & 1ull) ? ev1 : NEGV;
                float mx = wredmax(fmaxf(v0, v1));
                float p0 = __expf(v0 - mx), p1 = __expf(v1 - mx);
                float inv = 1.f / wredsum(p0 + p1);
                att[lane * P1PITCH + e]        = p0 * inv;
                att[(lane + 32) * P1PITCH + e] = p1 * inv;
            }
        }
        __syncthreads();

        // ---- P2c: edge = att_edge @ xtp; warp owns 4 edge-rows (2 pairs); fused f2 ----
        {
            const int e0 = w * 4;
            u64 acc[2][4];
            #pragma unroll
            for (int p = 0; p < 2; p++)
                #pragma unroll
                for (int c = 0; c < 4; c++) acc[p][c] = 0;
            const u64* arb = (const u64*)(att + e0);
            const float4* xb = (const float4*)xtp + lane;
            #pragma unroll 2
            for (int j = 0; j < LLN; j++) {
                float4 vx = xb[j * 32];
                u64 bx0 = dup2(vx.x), bx1 = dup2(vx.y), bx2 = dup2(vx.z), bx3 = dup2(vx.w);
                u64 a0 = arb[j * (P1PITCH / 2)];
                u64 a1 = arb[j * (P1PITCH / 2) + 1];
                acc[0][0] = fma2(a0, bx0, acc[0][0]); acc[0][1] = fma2(a0, bx1, acc[0][1]);
                acc[0][2] = fma2(a0, bx2, acc[0][2]); acc[0][3] = fma2(a0, bx3, acc[0][3]);
                acc[1][0] = fma2(a1, bx0, acc[1][0]); acc[1][1] = fma2(a1, bx1, acc[1][1]);
                acc[1][2] = fma2(a1, bx2, acc[1][2]); acc[1][3] = fma2(a1, bx3, acc[1][3]);
            }
            float4 v3v = ((const float4*)g_v3[l])[lane];
            u64 v30 = dup2(v3v.x), v31 = dup2(v3v.y), v32 = dup2(v3v.z), v33 = dup2(v3v.w);
            #pragma unroll
            for (int p = 0; p < 2; p++) {
                float2 c0 = unp2(acc[p][0]), c1 = unp2(acc[p][1]);
                float2 c2 = unp2(acc[p][2]), c3 = unp2(acc[p][3]);
                *((float4*)(edge + (e0 + 2 * p) * DD) + lane)     = make_float4(c0.x, c1.x, c2.x, c3.x);
                *((float4*)(edge + (e0 + 2 * p + 1) * DD) + lane) = make_float4(c0.y, c1.y, c2.y, c3.y);
                u64 sv = 0;
                sv = fma2(acc[p][0], v30, sv);
                sv = fma2(acc[p][1], v31, sv);
                sv = fma2(acc[p][2], v32, sv);
                sv = fma2(acc[p][3], v33, sv);
                sv = wredsum2(sv);
                if (lane == 0) {
                    float2 s = unp2(sv);
                    f2[e0 + 2 * p]     = s.x;
                    f2[e0 + 2 * p + 1] = s.y;
                }
            }
        }
        __syncthreads();

        // ---- P2d: att_node softmax -> att2[i][j] (pitch 66); warp owns 2 rows ----
        {
            u64 mk0 = adjm[lane],      mk1 = adjm[lane + 32];
            u64 mk2 = adjm[lane + 64], mk3 = adjm[lane + 96];
            float fv0 = f2[lane], fv1 = f2[lane + 32], fv2 = f2[lane + 64], fv3 = f2[lane + 96];
            #pragma unroll
            for (int r = 0; r < 2; r++) {
                int j = w * 2 + r;
                float f1j = f1[j];
                float z0 = f1j + fv0; z0 = (z0 > 0.f) ? z0 : 0.2f * z0;
                float z1 = f1j + fv1; z1 = (z1 > 0.f) ? z1 : 0.2f * z1;
                float z2 = f1j + fv2; z2 = (z2 > 0.f) ? z2 : 0.2f * z2;
                float z3 = f1j + fv3; z3 = (z3 > 0.f) ? z3 : 0.2f * z3;
                float v0 = ((mk0 >> j) & 1ull) ? z0 : NEGV;
                float v1 = ((mk1 >> j) & 1ull) ? z1 : NEGV;
                float v2 = ((mk2 >> j) & 1ull) ? z2 : NEGV;
                float v3 = ((mk3 >> j) & 1ull) ? z3 : NEGV;
                float mx = wredmax(fmaxf(fmaxf(v0, v1), fmaxf(v2, v3)));
                float p0 = __expf(v0 - mx), p1 = __expf(v1 - mx);
                float p2 = __expf(v2 - mx), p3 = __expf(v3 - mx);
                float inv = 1.f / wredsum(p0 + p1 + p2 + p3);
                att[lane * P2PITCH + j]        = p0 * inv;
                att[(lane + 32) * P2PITCH + j] = p1 * inv;
                att[(lane + 64) * P2PITCH + j] = p2 * inv;
                att[(lane + 96) * P2PITCH + j] = p3 * inv;
            }
        }
        __syncthreads();

        // ---- P2e: x = att_node @ edge + residual ; split-K over edges ----
        {
            const int j0 = wg * 4;
            u64 acc[2][4];
            #pragma unroll
            for (int p = 0; p < 2; p++)
                #pragma unroll
                for (int c = 0; c < 4; c++) acc[p][c] = 0;
            const u64* arb = (const u64*)(att + j0) + ih * 64 * (P2PITCH / 2);
            const float4* eb = (const float4*)(edge + ih * 64 * DD) + lane;
            #pragma unroll 2
            for (int ii = 0; ii < 64; ii++) {
                float4 ev = eb[ii * 32];
                u64 be0 = dup2(ev.x), be1 = dup2(ev.y), be2 = dup2(ev.z), be3 = dup2(ev.w);
                u64 a0 = arb[ii * (P2PITCH / 2)];
                u64 a1 = arb[ii * (P2PITCH / 2) + 1];
                acc[0][0] = fma2(a0, be0, acc[0][0]); acc[0][1] = fma2(a0, be1, acc[0][1]);
                acc[0][2] = fma2(a0, be2, acc[0][2]); acc[0][3] = fma2(a0, be3, acc[0][3]);
                acc[1][0] = fma2(a1, be0, acc[1][0]); acc[1][1] = fma2(a1, be1, acc[1][1]);
                acc[1][2] = fma2(a1, be2, acc[1][2]); acc[1][3] = fma2(a1, be3, acc[1][3]);
            }
            __syncthreads();
            if (ih == 1) {
                #pragma unroll
                for (int p = 0; p < 2; p++)
                    #pragma unroll
                    for (int c = 0; c < 4; c++)
                        scr[wg * 256 + (p * 4 + c) * 32 + lane] = acc[p][c];
            }
            __syncthreads();
            if (ih == 0) {
                #pragma unroll
                for (int p = 0; p < 2; p++) {
                    #pragma unroll
                    for (int c = 0; c < 4; c++)
                        acc[p][c] = add2(acc[p][c], scr[wg * 256 + (p * 4 + c) * 32 + lane]);
                    int ra = j0 + 2 * p, rb = ra + 1;
                    int ia  = __ldg(inputs + b * LLN + ra);
                    int ib2 = __ldg(inputs + b * LLN + rb);
                    float4 ga = __ldg((const float4*)(emb + (size_t)ia * DD) + lane);
                    float4 gb = __ldg((const float4*)(emb + (size_t)ib2 * DD) + lane);
                    float2 c0 = unp2(acc[p][0]), c1 = unp2(acc[p][1]);
                    float2 c2 = unp2(acc[p][2]), c3 = unp2(acc[p][3]);
                    *((float4*)(xs + ra * DD) + lane) =
                        make_float4(c0.x + ga.x, c1.x + ga.y, c2.x + ga.z, c3.x + ga.w);
                    *((float4*)(xs + rb * DD) + lane) =
                        make_float4(c0.y + gb.x, c1.y + gb.y, c2.y + gb.z, c3.y + gb.w);
                }
            }
            __syncthreads();
        }
    }

    // ---- outputs: x, x, emb2[inputs] ; warp owns 2 rows ----
    #pragma unroll
    for (int r = 0; r < 2; r++) {
        int row = w * 2 + r;
        size_t base = ((size_t)b * LLN + row) * (size_t)DD + lane * 4;
        float4 v = *((const float4*)(xs + row * DD) + lane);
        *(float4*)(out + base) = v;
        *(float4*)(out + NOUT + base) = v;
        int idx = __ldg(inputs + b * LLN + row);
        float4 g = __ldg((const float4*)(emb2 + (size_t)idx * DD) + lane);
        *(float4*)(out + 2 * NOUT + base) = g;
    }
}

extern "C" void kernel_launch(void* const* d_in, const int* in_sizes, int n_in,
                              void* d_out, int out_size) {
    (void)in_sizes; (void)n_in; (void)out_size;
    const int*   inputs = (const int*)  d_in[0];
    const float* HT     = (const float*)d_in[1];
    const float* emb    = (const float*)d_in[4];
    const float* emb2   = (const float*)d_in[5];
    const float* g1_w2  = (const float*)d_in[6];
    const float* g1_w3  = (const float*)d_in[7];
    const float* g1_q   = (const float*)d_in[8];
    const float* g1_a   = (const float*)d_in[9];
    const float* g1_a2  = (const float*)d_in[10];
    const float* g2_w   = (const float*)d_in[11];
    const float* g2_w2  = (const float*)d_in[12];
    const float* g2_w3  = (const float*)d_in[13];
    const float* g2_q   = (const float*)d_in[14];
    const float* g2_a   = (const float*)d_in[15];
    const float* g2_a2  = (const float*)d_in[16];
    float* out = (float*)d_out;

    cudaFuncSetAttribute(session_main, cudaFuncAttributeMaxDynamicSharedMemorySize, SMEM_BYTES);

    precompute_kernel<<<1, 128>>>(g1_w2, g1_w3, g1_q, g1_a, g1_a2,
                                  g2_w2, g2_w3, g2_q, g2_a, g2_a2);
    session_main<<<BB, 1024, SMEM_BYTES>>>(inputs, HT, emb, emb2, g2_w, out);
}

// round 11
// speedup vs baseline: 1.1296x; 1.1296x over previous
#include <cuda_runtime.h>
#include <math.h>

#define BB   512
#define LLN  64
#define NEE  128
#define DD   128
#define NEGV (-9e15f)
#define NOUT ((size_t)BB * LLN * DD)

// smem layout (float offsets)
#define OFF_XS    0              // 8192 : x (64x128); becomes xt in-place in layer 2
#define OFF_EDGE  8192           // 16384: edge (128x128); stages g2w during transfer
#define OFF_RA    24576          // 8192 : region A = att1P / xsP / split-K scratch (4096 u64)
#define OFF_RB    32768          // 8192 : region B = att2P (4096 u64)
#define OFF_E1    40960          // 64
#define OFF_F1    41024          // 64
#define OFF_F2    41088          // 128
#define OFF_ADJ   41216          // u64[128] (256 floats)
#define SMEM_BYTES ((41472 + 32) * 4)

typedef unsigned long long u64;

// Per-layer precomputed projection vectors
__device__ float g_u1[2][DD];   // w2 @ a[d:2d]
__device__ float g_u2[2][DD];   // w2 @ a2[0:d]
__device__ float g_v3[2][DD];   // w3 @ a2[d:2d]
__device__ float g_qa[2];       // q . a[0:d]

__global__ void precompute_kernel(
    const float* __restrict__ w2_1, const float* __restrict__ w3_1,
    const float* __restrict__ q_1,  const float* __restrict__ a_1,  const float* __restrict__ a2_1,
    const float* __restrict__ w2_2, const float* __restrict__ w3_2,
    const float* __restrict__ q_2,  const float* __restrict__ a_2,  const float* __restrict__ a2_2)
{
    int k = threadIdx.x;  // 0..127
    const float* w2[2]  = {w2_1, w2_2};
    const float* w3[2]  = {w3_1, w3_2};
    const float* av[2]  = {a_1,  a_2};
    const float* a2v[2] = {a2_1, a2_2};
    const float* qv[2]  = {q_1,  q_2};

    for (int l = 0; l < 2; l++) {
        float u1 = 0.f, u2 = 0.f, v3 = 0.f;
        for (int j = 0; j < DD; j++) {
            float w2kj = w2[l][k * DD + j];
            u1 += w2kj * av[l][DD + j];
            u2 += w2kj * a2v[l][j];
            v3 += w3[l][k * DD + j] * a2v[l][DD + j];
        }
        g_u1[l][k] = u1;
        g_u2[l][k] = u2;
        g_v3[l][k] = v3;
    }
    __shared__ float red[DD];
    for (int l = 0; l < 2; l++) {
        red[k] = qv[l][k] * av[l][k];
        __syncthreads();
        if (k == 0) {
            float s = 0.f;
            for (int i = 0; i < DD; i++) s += red[i];
            g_qa[l] = s;
        }
        __syncthreads();
    }
}

// ---- packed fp32x2 helpers ----
__device__ __forceinline__ u64 fma2(u64 a, u64 b, u64 c) {
    u64 d;
    asm("fma.rn.f32x2 %0, %1, %2, %3;" : "=l"(d) : "l"(a), "l"(b), "l"(c));
    return d;
}
__device__ __forceinline__ u64 add2(u64 a, u64 b) {
    u64 d;
    asm("add.rn.f32x2 %0, %1, %2;" : "=l"(d) : "l"(a), "l"(b));
    return d;
}
__device__ __forceinline__ u64 dup2(float x) {
    u64 d;
    asm("mov.b64 %0, {%1, %2};" : "=l"(d) : "f"(x), "f"(x));
    return d;
}
__device__ __forceinline__ u64 pk2(float lo, float hi) {
    u64 d;
    asm("mov.b64 %0, {%1, %2};" : "=l"(d) : "f"(lo), "f"(hi));
    return d;
}
__device__ __forceinline__ float2 unp2(u64 a) {
    float lo, hi;
    asm("mov.b64 {%0, %1}, %2;" : "=f"(lo), "=f"(hi) : "l"(a));
    return make_float2(lo, hi);
}
__device__ __forceinline__ float wredsum(float v) {
    #pragma unroll
    for (int o = 16; o > 0; o >>= 1) v += __shfl_xor_sync(0xffffffffu, v, o);
    return v;
}
__device__ __forceinline__ float wredmax(float v) {
    #pragma unroll
    for (int o = 16; o > 0; o >>= 1) v = fmaxf(v, __shfl_xor_sync(0xffffffffu, v, o));
    return v;
}
__device__ __forceinline__ u64 wredsum2(u64 v) {
    #pragma unroll
    for (int o = 16; o > 0; o >>= 1) v = add2(v, __shfl_xor_sync(0xffffffffu, v, o));
    return v;
}

// One CTA per batch item, 512 threads = 16 warps.
__global__ void __launch_bounds__(512, 1) session_main(
    const int*   __restrict__ inputs,   // [B, L]
    const float* __restrict__ HT,       // [B, NE, L]
    const float* __restrict__ emb,      // [V, D]
    const float* __restrict__ emb2,     // [V, D]
    const float* __restrict__ g2w,      // [D, D]
    float*       __restrict__ out)
{
    extern __shared__ float sm[];
    float* xs   = sm + OFF_XS;
    float* edge = sm + OFF_EDGE;
    float* ra   = sm + OFF_RA;
    float* rb   = sm + OFF_RB;
    float* e1   = sm + OFF_E1;
    float* f1   = sm + OFF_F1;
    float* f2   = sm + OFF_F2;
    u64*   adjm = (u64*)(sm + OFF_ADJ);
    u64*   scr  = (u64*)ra;             // split-K scratch aliases region A

    const int b = blockIdx.x;
    const int t = threadIdx.x;
    const int w = t >> 5, lane = t & 31;
    const int wg = w & 7, ih = w >> 3;  // split-K: 8 row-groups x 2 k-halves

    // ---- P0: gather x = emb[inputs[b]]; warp owns rows 4w..4w+3 ----
    #pragma unroll
    for (int r = 0; r < 4; r++) {
        int row = w * 4 + r;
        int idx = __ldg(inputs + b * LLN + row);
        float4 v = __ldg((const float4*)(emb + (size_t)idx * DD) + lane);
        *((float4*)(xs + row * DD) + lane) = v;
    }

    // ---- P1: per-edge node bitmasks; warp owns edges 8w..8w+7 ----
    #pragma unroll
    for (int k = 0; k < 8; k++) {
        int e = w * 8 + k;
        const float* hr = HT + ((size_t)b * NEE + e) * LLN;
        float h0 = __ldg(hr + lane), h1 = __ldg(hr + lane + 32);
        unsigned m0 = __ballot_sync(0xffffffffu, h0 > 0.f);
        unsigned m1 = __ballot_sync(0xffffffffu, h1 > 0.f);
        if (lane == 0) adjm[e] = ((u64)m1 << 32) | (u64)m0;
    }
    __syncthreads();

    for (int l = 0; l < 2; l++) {

        // ---- P2a: e1[j] = lrelu(qa + xs[j].u1), f1[j] = xs[j].u2 (pre-transfer x) ----
        {
            float4 u1v = ((const float4*)g_u1[l])[lane];
            float4 u2v = ((const float4*)g_u2[l])[lane];
            float qa = g_qa[l];
            #pragma unroll
            for (int r = 0; r < 4; r++) {
                int row = w * 4 + r;
                float4 x4 = *((const float4*)(xs + row * DD) + lane);
                float s1 = x4.x * u1v.x + x4.y * u1v.y + x4.z * u1v.z + x4.w * u1v.w;
                float s2 = x4.x * u2v.x + x4.y * u2v.y + x4.z * u2v.z + x4.w * u2v.w;
                s1 = wredsum(s1);
                s2 = wredsum(s2);
                if (lane == 0) {
                    float v = qa + s1;
                    e1[row] = (v > 0.f) ? v : 0.2f * v;
                    f1[row] = s2;
                }
            }
        }
        __syncthreads();

        // ---- transfer (layer 2): xs <- xs @ g2w, in place, row-pair packed A ----
        if (l == 1) {
            // stage W into edge region (dead) and pack x row-pairs into region A
            {
                const float4* src = (const float4*)g2w;
                float4* dst = (float4*)edge;
                #pragma unroll
                for (int r = 0; r < 8; r++)
                    dst[w * 256 + r * 32 + lane] = __ldg(src + w * 256 + r * 32 + lane);
                #pragma unroll
                for (int pp = 0; pp < 2; pp++) {
                    int pr = w * 2 + pp;                       // row pair index
                    float4 a = *((const float4*)(xs + (2 * pr) * DD) + lane);
                    float4 bq = *((const float4*)(xs + (2 * pr + 1) * DD) + lane);
                    ulonglong2* dp = (ulonglong2*)ra + pr * 64 + lane * 2;
                    ulonglong2 v0, v1;
                    v0.x = pk2(a.x, bq.x); v0.y = pk2(a.y, bq.y);
                    v1.x = pk2(a.z, bq.z); v1.y = pk2(a.w, bq.w);
                    dp[0] = v0; dp[1] = v1;
                }
            }
            __syncthreads();
            const int r0 = wg * 8, rp0 = wg * 4;
            u64 acc[4][4];
            #pragma unroll
            for (int p = 0; p < 4; p++)
                #pragma unroll
                for (int c = 0; c < 4; c++) acc[p][c] = 0;
            const float4* wbase = (const float4*)(edge + ih * 64 * DD) + lane;
            const ulonglong2* ra2 = (const ulonglong2*)ra;
            #pragma unroll 2
            for (int kk = 0; kk < 64; kk += 2) {
                float4 wv0 = wbase[kk * 32];
                float4 wv1 = wbase[(kk + 1) * 32];
                u64 b00 = dup2(wv0.x), b01 = dup2(wv0.y), b02 = dup2(wv0.z), b03 = dup2(wv0.w);
                u64 b10 = dup2(wv1.x), b11 = dup2(wv1.y), b12 = dup2(wv1.z), b13 = dup2(wv1.w);
                #pragma unroll
                for (int p = 0; p < 4; p++) {
                    ulonglong2 xp = ra2[(rp0 + p) * 64 + ih * 32 + (kk >> 1)];
                    acc[p][0] = fma2(xp.x, b00, acc[p][0]); acc[p][1] = fma2(xp.x, b01, acc[p][1]);
                    acc[p][2] = fma2(xp.x, b02, acc[p][2]); acc[p][3] = fma2(xp.x, b03, acc[p][3]);
                    acc[p][0] = fma2(xp.y, b10, acc[p][0]); acc[p][1] = fma2(xp.y, b11, acc[p][1]);
                    acc[p][2] = fma2(xp.y, b12, acc[p][2]); acc[p][3] = fma2(xp.y, b13, acc[p][3]);
                }
            }
            __syncthreads();
            if (ih == 1) {
                #pragma unroll
                for (int p = 0; p < 4; p++)
                    #pragma unroll
                    for (int c = 0; c < 4; c++)
                        scr[wg * 512 + (p * 4 + c) * 32 + lane] = acc[p][c];
            }
            __syncthreads();
            if (ih == 0) {
                #pragma unroll
                for (int p = 0; p < 4; p++) {
                    #pragma unroll
                    for (int c = 0; c < 4; c++)
                        acc[p][c] = add2(acc[p][c], scr[wg * 512 + (p * 4 + c) * 32 + lane]);
                    float2 c0 = unp2(acc[p][0]), c1 = unp2(acc[p][1]);
                    float2 c2 = unp2(acc[p][2]), c3 = unp2(acc[p][3]);
                    *((float4*)(xs + (r0 + 2 * p) * DD) + lane)     = make_float4(c0.x, c1.x, c2.x, c3.x);
                    *((float4*)(xs + (r0 + 2 * p + 1) * DD) + lane) = make_float4(c0.y, c1.y, c2.y, c3.y);
                }
            }
            __syncthreads();
        }

        // ---- P2b: att_edge softmax -> att1P pairs in region A ----
        {
            float ev0 = e1[lane], ev1 = e1[lane + 32];
            #pragma unroll
            for (int k = 0; k < 8; k++) {
                int e = w * 8 + k;
                u64 m = adjm[e];
                float v0 = ((m >> lane) & 1ull) ? ev0 : NEGV;
                float v1 = ((m >> (lane + 32)) & 1ull) ? ev1 : NEGV;
                float mx = wredmax(fmaxf(v0, v1));
                float p0 = __expf(v0 - mx), p1 = __expf(v1 - mx);
                float inv = 1.f / wredsum(p0 + p1);
                int base = (e >> 1) * 128 + (e & 1);
                ra[base + lane * 2]        = p0 * inv;
                ra[base + (lane + 32) * 2] = p1 * inv;
            }
        }
        __syncthreads();

        // ---- P2c: edge = att_edge @ xs (pair-interleaved A); fused f2 = edge . v3 ----
        {
            const int e0 = w * 8, ep0 = w * 4;
            u64 acc[4][4];
            #pragma unroll
            for (int p = 0; p < 4; p++)
                #pragma unroll
                for (int c = 0; c < 4; c++) acc[p][c] = 0;
            const ulonglong2* ab = (const ulonglong2*)ra;
            const float4* xb = (const float4*)xs + lane;
            #pragma unroll 2
            for (int j = 0; j < LLN; j += 2) {
                float4 vx0 = xb[j * 32];
                float4 vx1 = xb[(j + 1) * 32];
                u64 b00 = dup2(vx0.x), b01 = dup2(vx0.y), b02 = dup2(vx0.z), b03 = dup2(vx0.w);
                u64 b10 = dup2(vx1.x), b11 = dup2(vx1.y), b12 = dup2(vx1.z), b13 = dup2(vx1.w);
                #pragma unroll
                for (int p = 0; p < 4; p++) {
                    ulonglong2 ap = ab[(ep0 + p) * 32 + (j >> 1)];
                    acc[p][0] = fma2(ap.x, b00, acc[p][0]); acc[p][1] = fma2(ap.x, b01, acc[p][1]);
                    acc[p][2] = fma2(ap.x, b02, acc[p][2]); acc[p][3] = fma2(ap.x, b03, acc[p][3]);
                    acc[p][0] = fma2(ap.y, b10, acc[p][0]); acc[p][1] = fma2(ap.y, b11, acc[p][1]);
                    acc[p][2] = fma2(ap.y, b12, acc[p][2]); acc[p][3] = fma2(ap.y, b13, acc[p][3]);
                }
            }
            float4 v3v = ((const float4*)g_v3[l])[lane];
            u64 v30 = dup2(v3v.x), v31 = dup2(v3v.y), v32 = dup2(v3v.z), v33 = dup2(v3v.w);
            #pragma unroll
            for (int p = 0; p < 4; p++) {
                float2 c0 = unp2(acc[p][0]), c1 = unp2(acc[p][1]);
                float2 c2 = unp2(acc[p][2]), c3 = unp2(acc[p][3]);
                *((float4*)(edge + (e0 + 2 * p) * DD) + lane)     = make_float4(c0.x, c1.x, c2.x, c3.x);
                *((float4*)(edge + (e0 + 2 * p + 1) * DD) + lane) = make_float4(c0.y, c1.y, c2.y, c3.y);
                u64 sv = 0;
                sv = fma2(acc[p][0], v30, sv);
                sv = fma2(acc[p][1], v31, sv);
                sv = fma2(acc[p][2], v32, sv);
                sv = fma2(acc[p][3], v33, sv);
                sv = wredsum2(sv);
                if (lane == 0) {
                    float2 s = unp2(sv);
                    f2[e0 + 2 * p]     = s.x;
                    f2[e0 + 2 * p + 1] = s.y;
                }
            }
        }
        __syncthreads();

        // ---- P2d: att_node softmax -> att2P pairs in region B ----
        {
            u64 mk0 = adjm[lane],      mk1 = adjm[lane + 32];
            u64 mk2 = adjm[lane + 64], mk3 = adjm[lane + 96];
            float fv0 = f2[lane], fv1 = f2[lane + 32], fv2 = f2[lane + 64], fv3 = f2[lane + 96];
            #pragma unroll
            for (int r = 0; r < 4; r++) {
                int j = w * 4 + r;
                float f1j = f1[j];
                float z0 = f1j + fv0; z0 = (z0 > 0.f) ? z0 : 0.2f * z0;
                float z1 = f1j + fv1; z1 = (z1 > 0.f) ? z1 : 0.2f * z1;
                float z2 = f1j + fv2; z2 = (z2 > 0.f) ? z2 : 0.2f * z2;
                float z3 = f1j + fv3; z3 = (z3 > 0.f) ? z3 : 0.2f * z3;
                float v0 = ((mk0 >> j) & 1ull) ? z0 : NEGV;
                float v1 = ((mk1 >> j) & 1ull) ? z1 : NEGV;
                float v2 = ((mk2 >> j) & 1ull) ? z2 : NEGV;
                float v3 = ((mk3 >> j) & 1ull) ? z3 : NEGV;
                float mx = wredmax(fmaxf(fmaxf(v0, v1), fmaxf(v2, v3)));
                float p0 = __expf(v0 - mx), p1 = __expf(v1 - mx);
                float p2 = __expf(v2 - mx), p3 = __expf(v3 - mx);
                float inv = 1.f / wredsum(p0 + p1 + p2 + p3);
                int base = (j >> 1) * 256 + (j & 1);
                rb[base + lane * 2]         = p0 * inv;
                rb[base + (lane + 32) * 2]  = p1 * inv;
                rb[base + (lane + 64) * 2]  = p2 * inv;
                rb[base + (lane + 96) * 2]  = p3 * inv;
            }
        }
        __syncthreads();

        // ---- P2e: x = att_node @ edge + residual ; split-K, pair-interleaved A ----
        {
            const int j0 = wg * 8, jp0 = wg * 4;
            u64 acc[4][4];
            #pragma unroll
            for (int p = 0; p < 4; p++)
                #pragma unroll
                for (int c = 0; c < 4; c++) acc[p][c] = 0;
            const ulonglong2* ab = (const ulonglong2*)rb;
            const float4* eb = (const float4*)(edge + ih * 64 * DD) + lane;
            #pragma unroll 2
            for (int ii = 0; ii < 64; ii += 2) {
                float4 ev0 = eb[ii * 32];
                float4 ev1 = eb[(ii + 1) * 32];
                u64 b00 = dup2(ev0.x), b01 = dup2(ev0.y), b02 = dup2(ev0.z), b03 = dup2(ev0.w);
                u64 b10 = dup2(ev1.x), b11 = dup2(ev1.y), b12 = dup2(ev1.z), b13 = dup2(ev1.w);
                #pragma unroll
                for (int p = 0; p < 4; p++) {
                    ulonglong2 ap = ab[(jp0 + p) * 64 + ih * 32 + (ii >> 1)];
                    acc[p][0] = fma2(ap.x, b00, acc[p][0]); acc[p][1] = fma2(ap.x, b01, acc[p][1]);
                    acc[p][2] = fma2(ap.x, b02, acc[p][2]); acc[p][3] = fma2(ap.x, b03, acc[p][3]);
                    acc[p][0] = fma2(ap.y, b10, acc[p][0]); acc[p][1] = fma2(ap.y, b11, acc[p][1]);
                    acc[p][2] = fma2(ap.y, b12, acc[p][2]); acc[p][3] = fma2(ap.y, b13, acc[p][3]);
                }
            }
            __syncthreads();
            if (ih == 1) {
                #pragma unroll
                for (int p = 0; p < 4; p++)
                    #pragma unroll
                    for (int c = 0; c < 4; c++)
                        scr[wg * 512 + (p * 4 + c) * 32 + lane] = acc[p][c];
            }
            __syncthreads();
            if (ih == 0) {
                #pragma unroll
                for (int p = 0; p < 4; p++) {
                    #pragma unroll
                    for (int c = 0; c < 4; c++)
                        acc[p][c] = add2(acc[p][c], scr[wg * 512 + (p * 4 + c) * 32 + lane]);
                    int raw = j0 + 2 * p, rbw = raw + 1;
                    int ia  = __ldg(inputs + b * LLN + raw);
                    int ib2 = __ldg(inputs + b * LLN + rbw);
                    float4 ga = __ldg((const float4*)(emb + (size_t)ia * DD) + lane);
                    float4 gb = __ldg((const float4*)(emb + (size_t)ib2 * DD) + lane);
                    float2 c0 = unp2(acc[p][0]), c1 = unp2(acc[p][1]);
                    float2 c2 = unp2(acc[p][2]), c3 = unp2(acc[p][3]);
                    *((float4*)(xs + raw * DD) + lane) =
                        make_float4(c0.x + ga.x, c1.x + ga.y, c2.x + ga.z, c3.x + ga.w);
                    *((float4*)(xs + rbw * DD) + lane) =
                        make_float4(c0.y + gb.x, c1.y + gb.y, c2.y + gb.z, c3.y + gb.w);
                }
            }
            __syncthreads();
        }
    }

    // ---- outputs: x, x, emb2[inputs] ----
    #pragma unroll
    for (int r = 0; r < 4; r++) {
        int row = w * 4 + r;
        size_t base = ((size_t)b * LLN + row) * (size_t)DD + lane * 4;
        float4 v = *((const float4*)(xs + row * DD) + lane);
        *(float4*)(out + base) = v;
        *(float4*)(out + NOUT + base) = v;
        int idx = __ldg(inputs + b * LLN + row);
        float4 g = __ldg((const float4*)(emb2 + (size_t)idx * DD) + lane);
        *(float4*)(out + 2 * NOUT + base) = g;
    }
}

extern "C" void kernel_launch(void* const* d_in, const int* in_sizes, int n_in,
                              void* d_out, int out_size) {
    (void)in_sizes; (void)n_in; (void)out_size;
    const int*   inputs = (const int*)  d_in[0];
    const float* HT     = (const float*)d_in[1];
    const float* emb    = (const float*)d_in[4];
    const float* emb2   = (const float*)d_in[5];
    const float* g1_w2  = (const float*)d_in[6];
    const float* g1_w3  = (const float*)d_in[7];
    const float* g1_q   = (const float*)d_in[8];
    const float* g1_a   = (const float*)d_in[9];
    const float* g1_a2  = (const float*)d_in[10];
    const float* g2_w   = (const float*)d_in[11];
    const float* g2_w2  = (const float*)d_in[12];
    const float* g2_w3  = (const float*)d_in[13];
    const float* g2_q   = (const float*)d_in[14];
    const float* g2_a   = (const float*)d_in[15];
    const float* g2_a2  = (const float*)d_in[16];
    float* out = (float*)d_out;

    cudaFuncSetAttribute(session_main, cudaFuncAttributeMaxDynamicSharedMemorySize, SMEM_BYTES);

    precompute_kernel<<<1, 128>>>(g1_w2, g1_w3, g1_q, g1_a, g1_a2,
                                  g2_w2, g2_w3, g2_q, g2_a, g2_a2);
    session_main<<<BB, 512, SMEM_BYTES>>>(inputs, HT, emb, emb2, g2_w, out);
}

// round 15
// speedup vs baseline: 1.1326x; 1.0027x over previous
#include <cuda_runtime.h>
#include <math.h>

#define BB   512
#define LLN  64
#define NEE  128
#define DD   128
#define NEGV (-9e15f)
#define NOUT ((size_t)BB * LLN * DD)

// smem layout (float offsets)
#define OFF_XS    0              // 8192 : x (64x128); becomes xt in-place in layer 2
#define OFF_EDGE  8192           // 16384: edge (128x128); stages g2w during transfer
#define OFF_RA    24576          // 8192 : region A = att1P / xsP / split-K scratch (4096 u64)
#define OFF_RB    32768          // 8192 : region B = att2P (4096 u64)
#define OFF_E1    40960          // 64
#define OFF_F1    41024          // 64
#define OFF_F2    41088          // 128
#define OFF_ADJ   41216          // u64[128] (256 floats)
#define SMEM_BYTES ((41472 + 32) * 4)

typedef unsigned long long u64;

// Per-layer precomputed projection vectors
__device__ float g_u1[2][DD];   // w2 @ a[d:2d]
__device__ float g_u2[2][DD];   // w2 @ a2[0:d]
__device__ float g_v3[2][DD];   // w3 @ a2[d:2d]
__device__ float g_qa[2];       // q . a[0:d]

__global__ void precompute_kernel(
    const float* __restrict__ w2_1, const float* __restrict__ w3_1,
    const float* __restrict__ q_1,  const float* __restrict__ a_1,  const float* __restrict__ a2_1,
    const float* __restrict__ w2_2, const float* __restrict__ w3_2,
    const float* __restrict__ q_2,  const float* __restrict__ a_2,  const float* __restrict__ a2_2)
{
    int k = threadIdx.x;  // 0..127
    const float* w2[2]  = {w2_1, w2_2};
    const float* w3[2]  = {w3_1, w3_2};
    const float* av[2]  = {a_1,  a_2};
    const float* a2v[2] = {a2_1, a2_2};
    const float* qv[2]  = {q_1,  q_2};

    for (int l = 0; l < 2; l++) {
        float u1 = 0.f, u2 = 0.f, v3 = 0.f;
        for (int j = 0; j < DD; j++) {
            float w2kj = w2[l][k * DD + j];
            u1 += w2kj * av[l][DD + j];
            u2 += w2kj * a2v[l][j];
            v3 += w3[l][k * DD + j] * a2v[l][DD + j];
        }
        g_u1[l][k] = u1;
        g_u2[l][k] = u2;
        g_v3[l][k] = v3;
    }
    __shared__ float red[DD];
    for (int l = 0; l < 2; l++) {
        red[k] = qv[l][k] * av[l][k];
        __syncthreads();
        if (k == 0) {
            float s = 0.f;
            for (int i = 0; i < DD; i++) s += red[i];
            g_qa[l] = s;
        }
        __syncthreads();
    }
}

// ---- packed fp32x2 helpers ----
__device__ __forceinline__ u64 fma2(u64 a, u64 b, u64 c) {
    u64 d;
    asm("fma.rn.f32x2 %0, %1, %2, %3;" : "=l"(d) : "l"(a), "l"(b), "l"(c));
    return d;
}
__device__ __forceinline__ u64 add2(u64 a, u64 b) {
    u64 d;
    asm("add.rn.f32x2 %0, %1, %2;" : "=l"(d) : "l"(a), "l"(b));
    return d;
}
__device__ __forceinline__ u64 dup2(float x) {
    u64 d;
    asm("mov.b64 %0, {%1, %2};" : "=l"(d) : "f"(x), "f"(x));
    return d;
}
__device__ __forceinline__ u64 pk2(float lo, float hi) {
    u64 d;
    asm("mov.b64 %0, {%1, %2};" : "=l"(d) : "f"(lo), "f"(hi));
    return d;
}
__device__ __forceinline__ float2 unp2(u64 a) {
    float lo, hi;
    asm("mov.b64 {%0, %1}, %2;" : "=f"(lo), "=f"(hi) : "l"(a));
    return make_float2(lo, hi);
}
__device__ __forceinline__ float wredsum(float v) {
    #pragma unroll
    for (int o = 16; o > 0; o >>= 1) v += __shfl_xor_sync(0xffffffffu, v, o);
    return v;
}
__device__ __forceinline__ float wredmax(float v) {
    #pragma unroll
    for (int o = 16; o > 0; o >>= 1) v = fmaxf(v, __shfl_xor_sync(0xffffffffu, v, o));
    return v;
}
__device__ __forceinline__ u64 wredsum2(u64 v) {
    #pragma unroll
    for (int o = 16; o > 0; o >>= 1) v = add2(v, __shfl_xor_sync(0xffffffffu, v, o));
    return v;
}

// One CTA per batch item, 512 threads = 16 warps.
__global__ void __launch_bounds__(512, 1) session_main(
    const int*   __restrict__ inputs,   // [B, L]
    const float* __restrict__ HT,       // [B, NE, L]
    const float* __restrict__ emb,      // [V, D]
    const float* __restrict__ emb2,     // [V, D]
    const float* __restrict__ g2w,      // [D, D]
    float*       __restrict__ out)
{
    extern __shared__ float sm[];
    float* xs   = sm + OFF_XS;
    float* edge = sm + OFF_EDGE;
    float* ra   = sm + OFF_RA;
    float* rb   = sm + OFF_RB;
    float* e1   = sm + OFF_E1;
    float* f1   = sm + OFF_F1;
    float* f2   = sm + OFF_F2;
    u64*   adjm = (u64*)(sm + OFF_ADJ);
    u64*   scr  = (u64*)ra;             // split-K scratch aliases region A

    const int b = blockIdx.x;
    const int t = threadIdx.x;
    const int w = t >> 5, lane = t & 31;
    const int wg = w & 7, ih = w >> 3;  // split-K: 8 row-groups x 2 k-halves

    // ---- P0: gather x = emb[inputs[b]]; warp owns rows 4w..4w+3 ----
    #pragma unroll
    for (int r = 0; r < 4; r++) {
        int row = w * 4 + r;
        int idx = __ldg(inputs + b * LLN + row);
        float4 v = __ldg((const float4*)(emb + (size_t)idx * DD) + lane);
        *((float4*)(xs + row * DD) + lane) = v;
    }

    // ---- P1: per-edge node bitmasks; warp owns edges 8w..8w+7 ----
    #pragma unroll
    for (int k = 0; k < 8; k++) {
        int e = w * 8 + k;
        const float* hr = HT + ((size_t)b * NEE + e) * LLN;
        float h0 = __ldg(hr + lane), h1 = __ldg(hr + lane + 32);
        unsigned m0 = __ballot_sync(0xffffffffu, h0 > 0.f);
        unsigned m1 = __ballot_sync(0xffffffffu, h1 > 0.f);
        if (lane == 0) adjm[e] = ((u64)m1 << 32) | (u64)m0;
    }
    __syncthreads();

    for (int l = 0; l < 2; l++) {

        // ---- P2a: e1[j] = lrelu(qa + xs[j].u1), f1[j] = xs[j].u2 (pre-transfer x) ----
        {
            float4 u1v = ((const float4*)g_u1[l])[lane];
            float4 u2v = ((const float4*)g_u2[l])[lane];
            float qa = g_qa[l];
            #pragma unroll
            for (int r = 0; r < 4; r++) {
                int row = w * 4 + r;
                float4 x4 = *((const float4*)(xs + row * DD) + lane);
                float s1 = x4.x * u1v.x + x4.y * u1v.y + x4.z * u1v.z + x4.w * u1v.w;
                float s2 = x4.x * u2v.x + x4.y * u2v.y + x4.z * u2v.z + x4.w * u2v.w;
                s1 = wredsum(s1);
                s2 = wredsum(s2);
                if (lane == 0) {
                    float v = qa + s1;
                    e1[row] = (v > 0.f) ? v : 0.2f * v;
                    f1[row] = s2;
                }
            }
        }
        __syncthreads();

        // ---- transfer (layer 2): xs <- xs @ g2w, in place, row-pair packed A ----
        if (l == 1) {
            // stage W into edge region (dead) and pack x row-pairs into region A
            {
                const float4* src = (const float4*)g2w;
                float4* dst = (float4*)edge;
                #pragma unroll
                for (int r = 0; r < 8; r++)
                    dst[w * 256 + r * 32 + lane] = __ldg(src + w * 256 + r * 32 + lane);
                #pragma unroll
                for (int pp = 0; pp < 2; pp++) {
                    int pr = w * 2 + pp;                       // row pair index
                    float4 a = *((const float4*)(xs + (2 * pr) * DD) + lane);
                    float4 bq = *((const float4*)(xs + (2 * pr + 1) * DD) + lane);
                    ulonglong2* dp = (ulonglong2*)ra + pr * 64 + lane * 2;
                    ulonglong2 v0, v1;
                    v0.x = pk2(a.x, bq.x); v0.y = pk2(a.y, bq.y);
                    v1.x = pk2(a.z, bq.z); v1.y = pk2(a.w, bq.w);
                    dp[0] = v0; dp[1] = v1;
                }
            }
            __syncthreads();
            const int r0 = wg * 8, rp0 = wg * 4;
            u64 acc[4][4];
            #pragma unroll
            for (int p = 0; p < 4; p++)
                #pragma unroll
                for (int c = 0; c < 4; c++) acc[p][c] = 0;
            const float4* wbase = (const float4*)(edge + ih * 64 * DD) + lane;
            const ulonglong2* ra2 = (const ulonglong2*)ra;
            #pragma unroll 2
            for (int kk = 0; kk < 64; kk += 2) {
                float4 wv0 = wbase[kk * 32];
                float4 wv1 = wbase[(kk + 1) * 32];
                u64 b00 = dup2(wv0.x), b01 = dup2(wv0.y), b02 = dup2(wv0.z), b03 = dup2(wv0.w);
                u64 b10 = dup2(wv1.x), b11 = dup2(wv1.y), b12 = dup2(wv1.z), b13 = dup2(wv1.w);
                #pragma unroll
                for (int p = 0; p < 4; p++) {
                    ulonglong2 xp = ra2[(rp0 + p) * 64 + ih * 32 + (kk >> 1)];
                    acc[p][0] = fma2(xp.x, b00, acc[p][0]); acc[p][1] = fma2(xp.x, b01, acc[p][1]);
                    acc[p][2] = fma2(xp.x, b02, acc[p][2]); acc[p][3] = fma2(xp.x, b03, acc[p][3]);
                    acc[p][0] = fma2(xp.y, b10, acc[p][0]); acc[p][1] = fma2(xp.y, b11, acc[p][1]);
                    acc[p][2] = fma2(xp.y, b12, acc[p][2]); acc[p][3] = fma2(xp.y, b13, acc[p][3]);
                }
            }
            __syncthreads();
            if (ih == 1) {
                #pragma unroll
                for (int p = 0; p < 4; p++)
                    #pragma unroll
                    for (int c = 0; c < 4; c++)
                        scr[wg * 512 + (p * 4 + c) * 32 + lane] = acc[p][c];
            }
            __syncthreads();
            if (ih == 0) {
                #pragma unroll
                for (int p = 0; p < 4; p++) {
                    #pragma unroll
                    for (int c = 0; c < 4; c++)
                        acc[p][c] = add2(acc[p][c], scr[wg * 512 + (p * 4 + c) * 32 + lane]);
                    float2 c0 = unp2(acc[p][0]), c1 = unp2(acc[p][1]);
                    float2 c2 = unp2(acc[p][2]), c3 = unp2(acc[p][3]);
                    *((float4*)(xs + (r0 + 2 * p) * DD) + lane)     = make_float4(c0.x, c1.x, c2.x, c3.x);
                    *((float4*)(xs + (r0 + 2 * p + 1) * DD) + lane) = make_float4(c0.y, c1.y, c2.y, c3.y);
                }
            }
            __syncthreads();
        }

        // ---- P2b: att_edge softmax -> att1P pairs in region A ----
        {
            float ev0 = e1[lane], ev1 = e1[lane + 32];
            #pragma unroll
            for (int k = 0; k < 8; k++) {
                int e = w * 8 + k;
                u64 m = adjm[e];
                float v0 = ((m >> lane) & 1ull) ? ev0 : NEGV;
                float v1 = ((m >> (lane + 32)) & 1ull) ? ev1 : NEGV;
                float mx = wredmax(fmaxf(v0, v1));
                float p0 = __expf(v0 - mx), p1 = __expf(v1 - mx);
                float inv = 1.f / wredsum(p0 + p1);
                int base = (e >> 1) * 128 + (e & 1);
                ra[base + lane * 2]        = p0 * inv;
                ra[base + (lane + 32) * 2] = p1 * inv;
            }
        }
        __syncthreads();

        // ---- P2c: edge = att_edge @ xs (pair-interleaved A); fused f2 = edge . v3 ----
        {
            const int e0 = w * 8, ep0 = w * 4;
            u64 acc[4][4];
            #pragma unroll
            for (int p = 0; p < 4; p++)
                #pragma unroll
                for (int c = 0; c < 4; c++) acc[p][c] = 0;
            const ulonglong2* ab = (const ulonglong2*)ra;
            const float4* xb = (const float4*)xs + lane;
            #pragma unroll 2
            for (int j = 0; j < LLN; j += 2) {
                float4 vx0 = xb[j * 32];
                float4 vx1 = xb[(j + 1) * 32];
                u64 b00 = dup2(vx0.x), b01 = dup2(vx0.y), b02 = dup2(vx0.z), b03 = dup2(vx0.w);
                u64 b10 = dup2(vx1.x), b11 = dup2(vx1.y), b12 = dup2(vx1.z), b13 = dup2(vx1.w);
                #pragma unroll
                for (int p = 0; p < 4; p++) {
                    ulonglong2 ap = ab[(ep0 + p) * 32 + (j >> 1)];
                    acc[p][0] = fma2(ap.x, b00, acc[p][0]); acc[p][1] = fma2(ap.x, b01, acc[p][1]);
                    acc[p][2] = fma2(ap.x, b02, acc[p][2]); acc[p][3] = fma2(ap.x, b03, acc[p][3]);
                    acc[p][0] = fma2(ap.y, b10, acc[p][0]); acc[p][1] = fma2(ap.y, b11, acc[p][1]);
                    acc[p][2] = fma2(ap.y, b12, acc[p][2]); acc[p][3] = fma2(ap.y, b13, acc[p][3]);
                }
            }
            float4 v3v = ((const float4*)g_v3[l])[lane];
            u64 v30 = dup2(v3v.x), v31 = dup2(v3v.y), v32 = dup2(v3v.z), v33 = dup2(v3v.w);
            #pragma unroll
            for (int p = 0; p < 4; p++) {
                float2 c0 = unp2(acc[p][0]), c1 = unp2(acc[p][1]);
                float2 c2 = unp2(acc[p][2]), c3 = unp2(acc[p][3]);
                *((float4*)(edge + (e0 + 2 * p) * DD) + lane)     = make_float4(c0.x, c1.x, c2.x, c3.x);
                *((float4*)(edge + (e0 + 2 * p + 1) * DD) + lane) = make_float4(c0.y, c1.y, c2.y, c3.y);
                u64 sv = 0;
                sv = fma2(acc[p][0], v30, sv);
                sv = fma2(acc[p][1], v31, sv);
                sv = fma2(acc[p][2], v32, sv);
                sv = fma2(acc[p][3], v33, sv);
                sv = wredsum2(sv);
                if (lane == 0) {
                    float2 s = unp2(sv);
                    f2[e0 + 2 * p]     = s.x;
                    f2[e0 + 2 * p + 1] = s.y;
                }
            }
        }
        __syncthreads();

        // ---- P2d: att_node softmax -> att2P pairs in region B ----
        {
            u64 mk0 = adjm[lane],      mk1 = adjm[lane + 32];
            u64 mk2 = adjm[lane + 64], mk3 = adjm[lane + 96];
            float fv0 = f2[lane], fv1 = f2[lane + 32], fv2 = f2[lane + 64], fv3 = f2[lane + 96];
            #pragma unroll
            for (int r = 0; r < 4; r++) {
                int j = w * 4 + r;
                float f1j = f1[j];
                float z0 = f1j + fv0; z0 = (z0 > 0.f) ? z0 : 0.2f * z0;
                float z1 = f1j + fv1; z1 = (z1 > 0.f) ? z1 : 0.2f * z1;
                float z2 = f1j + fv2; z2 = (z2 > 0.f) ? z2 : 0.2f * z2;
                float z3 = f1j + fv3; z3 = (z3 > 0.f) ? z3 : 0.2f * z3;
                float v0 = ((mk0 >> j) & 1ull) ? z0 : NEGV;
                float v1 = ((mk1 >> j) & 1ull) ? z1 : NEGV;
                float v2 = ((mk2 >> j) & 1ull) ? z2 : NEGV;
                float v3 = ((mk3 >> j) & 1ull) ? z3 : NEGV;
                float mx = wredmax(fmaxf(fmaxf(v0, v1), fmaxf(v2, v3)));
                float p0 = __expf(v0 - mx), p1 = __expf(v1 - mx);
                float p2 = __expf(v2 - mx), p3 = __expf(v3 - mx);
                float inv = 1.f / wredsum(p0 + p1 + p2 + p3);
                int base = (j >> 1) * 256 + (j & 1);
                rb[base + lane * 2]         = p0 * inv;
                rb[base + (lane + 32) * 2]  = p1 * inv;
                rb[base + (lane + 64) * 2]  = p2 * inv;
                rb[base + (lane + 96) * 2]  = p3 * inv;
            }
        }
        __syncthreads();

        // ---- P2e: x = att_node @ edge + residual ; split-K, pair-interleaved A ----
        {
            const int j0 = wg * 8, jp0 = wg * 4;
            u64 acc[4][4];
            #pragma unroll
            for (int p = 0; p < 4; p++)
                #pragma unroll
                for (int c = 0; c < 4; c++) acc[p][c] = 0;
            const ulonglong2* ab = (const ulonglong2*)rb;
            const float4* eb = (const float4*)(edge + ih * 64 * DD) + lane;
            #pragma unroll 2
            for (int ii = 0; ii < 64; ii += 2) {
                float4 ev0 = eb[ii * 32];
                float4 ev1 = eb[(ii + 1) * 32];
                u64 b00 = dup2(ev0.x), b01 = dup2(ev0.y), b02 = dup2(ev0.z), b03 = dup2(ev0.w);
                u64 b10 = dup2(ev1.x), b11 = dup2(ev1.y), b12 = dup2(ev1.z), b13 = dup2(ev1.w);
                #pragma unroll
                for (int p = 0; p < 4; p++) {
                    ulonglong2 ap = ab[(jp0 + p) * 64 + ih * 32 + (ii >> 1)];
                    acc[p][0] = fma2(ap.x, b00, acc[p][0]); acc[p][1] = fma2(ap.x, b01, acc[p][1]);
                    acc[p][2] = fma2(ap.x, b02, acc[p][2]); acc[p][3] = fma2(ap.x, b03, acc[p][3]);
                    acc[p][0] = fma2(ap.y, b10, acc[p][0]); acc[p][1] = fma2(ap.y, b11, acc[p][1]);
                    acc[p][2] = fma2(ap.y, b12, acc[p][2]); acc[p][3] = fma2(ap.y, b13, acc[p][3]);
                }
            }
            __syncthreads();
            if (ih == 1) {
                #pragma unroll
                for (int p = 0; p < 4; p++)
                    #pragma unroll
                    for (int c = 0; c < 4; c++)
                        scr[wg * 512 + (p * 4 + c) * 32 + lane] = acc[p][c];
            }
            __syncthreads();
            if (ih == 0) {
                #pragma unroll
                for (int p = 0; p < 4; p++) {
                    #pragma unroll
                    for (int c = 0; c < 4; c++)
                        acc[p][c] = add2(acc[p][c], scr[wg * 512 + (p * 4 + c) * 32 + lane]);
                    int raw = j0 + 2 * p, rbw = raw + 1;
                    int ia  = __ldg(inputs + b * LLN + raw);
                    int ib2 = __ldg(inputs + b * LLN + rbw);
                    float4 ga = __ldg((const float4*)(emb + (size_t)ia * DD) + lane);
                    float4 gb = __ldg((const float4*)(emb + (size_t)ib2 * DD) + lane);
                    float2 c0 = unp2(acc[p][0]), c1 = unp2(acc[p][1]);
                    float2 c2 = unp2(acc[p][2]), c3 = unp2(acc[p][3]);
                    *((float4*)(xs + raw * DD) + lane) =
                        make_float4(c0.x + ga.x, c1.x + ga.y, c2.x + ga.z, c3.x + ga.w);
                    *((float4*)(xs + rbw * DD) + lane) =
                        make_float4(c0.y + gb.x, c1.y + gb.y, c2.y + gb.z, c3.y + gb.w);
                }
            }
            __syncthreads();
        }
    }

    // ---- outputs: x, x, emb2[inputs] ----
    #pragma unroll
    for (int r = 0; r < 4; r++) {
        int row = w * 4 + r;
        size_t base = ((size_t)b * LLN + row) * (size_t)DD + lane * 4;
        float4 v = *((const float4*)(xs + row * DD) + lane);
        *(float4*)(out + base) = v;
        *(float4*)(out + NOUT + base) = v;
        int idx = __ldg(inputs + b * LLN + row);
        float4 g = __ldg((const float4*)(emb2 + (size_t)idx * DD) + lane);
        *(float4*)(out + 2 * NOUT + base) = g;
    }
}

extern "C" void kernel_launch(void* const* d_in, const int* in_sizes, int n_in,
                              void* d_out, int out_size) {
    (void)in_sizes; (void)n_in; (void)out_size;
    const int*   inputs = (const int*)  d_in[0];
    const float* HT     = (const float*)d_in[1];
    const float* emb    = (const float*)d_in[4];
    const float* emb2   = (const float*)d_in[5];
    const float* g1_w2  = (const float*)d_in[6];
    const float* g1_w3  = (const float*)d_in[7];
    const float* g1_q   = (const float*)d_in[8];
    const float* g1_a   = (const float*)d_in[9];
    const float* g1_a2  = (const float*)d_in[10];
    const float* g2_w   = (const float*)d_in[11];
    const float* g2_w2  = (const float*)d_in[12];
    const float* g2_w3  = (const float*)d_in[13];
    const float* g2_q   = (const float*)d_in[14];
    const float* g2_a   = (const float*)d_in[15];
    const float* g2_a2  = (const float*)d_in[16];
    float* out = (float*)d_out;

    cudaFuncSetAttribute(session_main, cudaFuncAttributeMaxDynamicSharedMemorySize, SMEM_BYTES);

    precompute_kernel<<<1, 128>>>(g1_w2, g1_w3, g1_q, g1_a, g1_a2,
                                  g2_w2, g2_w3, g2_q, g2_a, g2_a2);
    session_main<<<BB, 512, SMEM_BYTES>>>(inputs, HT, emb, emb2, g2_w, out);
}